// round 5
// baseline (speedup 1.0000x reference)
#include <cuda_runtime.h>

// Haar DWT2: x[8,64,512,512] f32 -> (ll, lh, hl, hh) each [8,64,256,256],
// concatenated into d_out in that order.

#define IN_W      512
#define OUT_W     256
#define IN_PLANE  (512*512)
#define OUT_PLANE (256*256)
#define SUBBAND   (512*256*256)

// Each thread: 4 output rows x 4 output cols (8 input rows x 8 input cols).
// 16 front-batched 128-bit loads -> 16 stores: 8KB read burst then 8KB write
// burst per warp, to amortize DRAM R/W turnaround.
// Total threads = 512 planes * 64 row-quads * 64 = 2,097,152.
__global__ void __launch_bounds__(256) haar_dwt2_kernel(
    const float* __restrict__ x, float* __restrict__ out)
{
    unsigned idx = blockIdx.x * blockDim.x + threadIdx.x;   // < 2097152
    unsigned t   = idx & 63u;          // 0..63  -> output cols [4t, 4t+3]
    unsigned oq  = (idx >> 6) & 63u;   // 0..63  output row quad (rows 4oq..4oq+3)
    unsigned bc  = idx >> 12;          // 0..511 plane

    const float* base = x + (size_t)bc * IN_PLANE + (size_t)(8u * oq) * IN_W + 8u * t;

    // 16 independent 128-bit streaming loads, front-batched.
    float4 r[8][2];
#pragma unroll
    for (int i = 0; i < 8; i++) {
        r[i][0] = __ldcs(reinterpret_cast<const float4*>(base + i * IN_W));
        r[i][1] = __ldcs(reinterpret_cast<const float4*>(base + i * IN_W + 4));
    }

    const float S = 0.5f;
    size_t obase = (size_t)bc * OUT_PLANE + (size_t)(4u * oq) * OUT_W + 4u * t;

    float4 LL[4], LH[4], HL[4], HH[4];
#pragma unroll
    for (int j = 0; j < 4; j++) {       // output row j <- input rows 2j, 2j+1
        const float4 t0a = r[2*j][0],   t0b = r[2*j][1];
        const float4 t1a = r[2*j+1][0], t1b = r[2*j+1][1];
        float a[4] = { t0a.x, t0a.z, t0b.x, t0b.z };
        float b[4] = { t0a.y, t0a.w, t0b.y, t0b.w };
        float c[4] = { t1a.x, t1a.z, t1b.x, t1b.z };
        float d[4] = { t1a.y, t1a.w, t1b.y, t1b.w };
        float* ll = &LL[j].x; float* lh = &LH[j].x;
        float* hl = &HL[j].x; float* hh = &HH[j].x;
#pragma unroll
        for (int k = 0; k < 4; k++) {
            float ab  = a[k] + b[k], cd  = c[k] + d[k];
            float amb = a[k] - b[k], cmd = c[k] - d[k];
            ll[k] = (ab + cd) * S;
            lh[k] = (ab - cd) * S;
            hl[k] = (amb + cmd) * S;
            hh[k] = (amb - cmd) * S;
        }
    }

    // 16 stores, batched after all loads/compute.
#pragma unroll
    for (int j = 0; j < 4; j++) {
        size_t o = obase + (size_t)j * OUT_W;
        __stcs(reinterpret_cast<float4*>(out + o),                      LL[j]);
        __stcs(reinterpret_cast<float4*>(out + o + (size_t)SUBBAND),    LH[j]);
        __stcs(reinterpret_cast<float4*>(out + o + (size_t)SUBBAND*2),  HL[j]);
        __stcs(reinterpret_cast<float4*>(out + o + (size_t)SUBBAND*3),  HH[j]);
    }
}

extern "C" void kernel_launch(void* const* d_in, const int* in_sizes, int n_in,
                              void* d_out, int out_size)
{
    const float* x = (const float*)d_in[0];
    float* out = (float*)d_out;
    // 2,097,152 threads / 256 = 8192 blocks
    haar_dwt2_kernel<<<8192, 256>>>(x, out);
}